// round 10
// baseline (speedup 1.0000x reference)
#include <cuda_runtime.h>
#include <cstdint>

// B=256, T=64 (K), S=16, U=4 -> P=256 pixels, O=1024 outputs/pixel.
//
// R9 finding: smem crossbar (L1=89.6%) binds; bytes charged per-lane. Minimize
// LDS bytes per FFMA2: thread tile 16b x 8o with b-pair packed fma.rn.f32x2
// -> 1.5 B/FFMA2 (vs 3.0 in R9); fma pipe becomes the binding resource.
//
// kernel 1: transpose x (B,T,S,S) -> g_xT32[p][t][b] (fp32; b contiguous, so
//           b-pair f32x2 operands are natural 8B loads).
// kernel 2: CTA = (bn 8, p 256): C[256 b x 128 o] = A @ W^T + bias.
//           As = raw copy of [64 t][256 b] slice (cp.async, 64 KB).
//           Wp[k][o_sw] transposed W, o_sw = (o&7)*16 + (o>>3), stride 129
//           (B LDS.32 conflict-free across the 16 'to' lanes).
//           Thread: 16 b (8 pairs) x 8 o, acc2[8][8] f32x2 = (C[b][o], C[b+1][o]).
//           Epilogue: two STG.128 per b-row into pixel-shuffle layout.

__device__ float g_xT32[256 * 64 * 256];  // [p][t][b], 16 MB

__device__ __forceinline__ uint32_t smem_u32(const void* p) {
    uint32_t a;
    asm("{ .reg .u64 t; cvta.to.shared.u64 t, %1; cvt.u32.u64 %0, t; }" : "=r"(a) : "l"(p));
    return a;
}
__device__ __forceinline__ void cp16(uint32_t sdst, const void* g) {
    asm volatile("cp.async.cg.shared.global [%0], [%1], 16;" :: "r"(sdst), "l"(g));
}
__device__ __forceinline__ unsigned long long dupf2(float v) {
    unsigned long long r;
    asm("mov.b64 %0, {%1, %1};" : "=l"(r) : "f"(v));
    return r;
}
__device__ __forceinline__ float2 unpackf2(unsigned long long v) {
    float2 r;
    asm("mov.b64 {%0, %1}, %2;" : "=f"(r.x), "=f"(r.y) : "l"(v));
    return r;
}

// ---------------------------------------------------------------------------
// Transpose: x[b][t][p] -> g_xT32[p*16384 + t*256 + b]
// grid (8 p-tiles, 8 b-tiles, 64 t), block (32, 8)
// ---------------------------------------------------------------------------
__global__ void transpose32_kernel(const float* __restrict__ x) {
    __shared__ float tile[32][33];
    int p0 = blockIdx.x * 32, b0 = blockIdx.y * 32, t = blockIdx.z;
    int tx = threadIdx.x, ty = threadIdx.y;
#pragma unroll
    for (int k = 0; k < 4; k++) {
        int br = ty + k * 8;
        tile[br][tx] = x[(size_t)(b0 + br) * 16384 + (size_t)t * 256 + p0 + tx];
    }
    __syncthreads();
#pragma unroll
    for (int k = 0; k < 4; k++) {
        int pr = ty + k * 8;
        g_xT32[(size_t)(p0 + pr) * 16384 + (size_t)t * 256 + b0 + tx] = tile[tx][pr];
    }
}

// ---------------------------------------------------------------------------
// GEMM: C[256 b x 128 o] per CTA. 256 threads: tb = tid>>4 (16 b-rows each),
// to = tid&15 (8 o each). b-pair FFMA2, acc2[8 pairs][8 o].
// ---------------------------------------------------------------------------
#define WPROW 129
#define AS_F (64 * 256)            // 16384 floats = 64 KB
#define WP_F (64 * WPROW)          // 8256 floats
#define SMEM_BYTES ((AS_F + WP_F + 128) * 4)

__global__ __launch_bounds__(256, 1) void gemm_kernel(const float* __restrict__ Wg_all,
                                                      const float* __restrict__ bias,
                                                      float* __restrict__ out) {
    extern __shared__ float smem[];
    float* As = smem;                   // [64 t][256 b], raw copy
    float* Wp = smem + AS_F;            // [64 k][WPROW], o-swizzled
    float* bias_s = smem + AS_F + WP_F; // [128]

    const int bn = blockIdx.x;   // 0..7 (o tile of 128)
    const int p  = blockIdx.y;
    const int tid = threadIdx.x;
    const int tb = tid >> 4;     // b rows tb*16 .. tb*16+15
    const int to = tid & 15;     // o = bn*128 + to*8 + j, j=0..7

    // A: linear 64 KB copy of g_xT32 p-slice
    const float* Ag = g_xT32 + ((size_t)p << 14);
    uint32_t sA = smem_u32(As);
#pragma unroll
    for (int i = 0; i < 16; i++) {
        int idx = tid + i * 256;         // 4096 chunks of 16B
        cp16(sA + idx * 16, Ag + idx * 4);
    }
    if (tid < 32) cp16(smem_u32(bias_s) + tid * 16, bias + (size_t)p * 1024 + bn * 128 + tid * 4);
    asm volatile("cp.async.commit_group;");

    // W: [128 o][64 k] -> Wp[k][o_sw], o_sw = (o&7)*16 + (o>>3)
    const float* Wg = Wg_all + ((size_t)p << 16) + (size_t)(bn * 128) * 64;
#pragma unroll
    for (int i = 0; i < 8; i++) {
        int idx = tid + i * 256;          // 2048 float4s
        int o = idx >> 4;                 // 0..127
        int kc = (idx & 15) << 2;         // 0..60
        float4 v = *(const float4*)(Wg + o * 64 + kc);
        int o_sw = ((o & 7) << 4) + (o >> 3);
        Wp[(kc + 0) * WPROW + o_sw] = v.x;
        Wp[(kc + 1) * WPROW + o_sw] = v.y;
        Wp[(kc + 2) * WPROW + o_sw] = v.z;
        Wp[(kc + 3) * WPROW + o_sw] = v.w;
    }
    asm volatile("cp.async.wait_group 0;");
    __syncthreads();

    unsigned long long acc2[8][8];
#pragma unroll
    for (int i = 0; i < 8; i++)
#pragma unroll
        for (int j = 0; j < 8; j++) acc2[i][j] = 0ull;

    const float* Abase = As + tb * 16;
    const float* Bbase = Wp + to;

#pragma unroll 4
    for (int k = 0; k < 64; k++) {
        const ulonglong2* Ak = (const ulonglong2*)(Abase + k * 256);
        ulonglong2 A0 = Ak[0], A1 = Ak[1], A2 = Ak[2], A3 = Ak[3];
        unsigned long long a2[8] = {A0.x, A0.y, A1.x, A1.y, A2.x, A2.y, A3.x, A3.y};
        const float* Bk = Bbase + k * WPROW;
        unsigned long long bd[8];
#pragma unroll
        for (int j = 0; j < 8; j++) bd[j] = dupf2(Bk[j * 16]);
#pragma unroll
        for (int i = 0; i < 8; i++)
#pragma unroll
            for (int j = 0; j < 8; j++) {
                asm("fma.rn.f32x2 %0, %1, %2, %0;"
                    : "+l"(acc2[i][j]) : "l"(a2[i]), "l"(bd[j]));
            }
    }

    // Epilogue: o0 = bn*128 + to*8; j 0..3 -> quad at (t,ui), j 4..7 -> (t,ui+1)
    const int i4 = (p >> 4) << 2, j4 = (p & 15) << 2;
    int o0 = bn * 128 + to * 8;
    int t  = o0 >> 4;
    int ui = (o0 >> 2) & 3;               // 0 or 2
    int coloff0 = t * 4096 + (i4 + ui) * 64 + j4;
    int coloff1 = coloff0 + 64;           // ui+1
    float4 bv0 = *(const float4*)&bias_s[to * 8];
    float4 bv1 = *(const float4*)&bias_s[to * 8 + 4];
#pragma unroll
    for (int i = 0; i < 8; i++) {
        float2 c[8];
#pragma unroll
        for (int j = 0; j < 8; j++) c[j] = unpackf2(acc2[i][j]);
        size_t r0 = (size_t)(tb * 16 + 2 * i) * 262144;
        size_t r1 = r0 + 262144;
        *(float4*)(out + r0 + coloff0) =
            make_float4(c[0].x + bv0.x, c[1].x + bv0.y, c[2].x + bv0.z, c[3].x + bv0.w);
        *(float4*)(out + r0 + coloff1) =
            make_float4(c[4].x + bv1.x, c[5].x + bv1.y, c[6].x + bv1.z, c[7].x + bv1.w);
        *(float4*)(out + r1 + coloff0) =
            make_float4(c[0].y + bv0.x, c[1].y + bv0.y, c[2].y + bv0.z, c[3].y + bv0.w);
        *(float4*)(out + r1 + coloff1) =
            make_float4(c[4].y + bv1.x, c[5].y + bv1.y, c[6].y + bv1.z, c[7].y + bv1.w);
    }
}

extern "C" void kernel_launch(void* const* d_in, const int* in_sizes, int n_in,
                              void* d_out, int out_size) {
    const float* x = (const float*)d_in[0];   // (256, 64, 16, 16)
    const float* W = (const float*)d_in[1];   // (256, 1024, 64)
    const float* b = (const float*)d_in[2];   // (256, 1024)
    float* out = (float*)d_out;               // (256, 64, 64, 64)
    (void)in_sizes; (void)n_in; (void)out_size;

    cudaFuncSetAttribute(gemm_kernel, cudaFuncAttributeMaxDynamicSharedMemorySize, SMEM_BYTES);

    transpose32_kernel<<<dim3(8, 8, 64), dim3(32, 8)>>>(x);
    gemm_kernel<<<dim3(8, 256), 256, SMEM_BYTES>>>(W, b, out);
}

// round 11
// speedup vs baseline: 1.4181x; 1.4181x over previous
#include <cuda_runtime.h>
#include <cstdint>

// B=256, T=64 (K), S=16, U=4 -> P=256 pixels, O=1024 outputs/pixel.
//
// Calibrated model: fma pipe floor 227k cyc (fma.rn.f32x2, 128 MAC/cyc/SM);
// smem crossbar cost = per-thread-LDS-bytes/4 wf per warp (no dedup).
// Balanced design: thread tile 8b(4 pairs) x 8o -> 16 wf vs 16 fma-cyc per
// warp-k, acc 64 regs -> ~110 total -> 2 CTAs/SM (16 warps) for latency cover.
//
// kernel 1: transpose x (B,T,S,S) -> g_xT32[p][t][b] (b contiguous -> natural
//           b-pair f32x2 A operands).
// kernel 2: CTA = (bn 16, p 256): C[256 b x 64 o] = A @ W^T + bias.
//           As[64 k][256 b] raw cp.async copy (64 KB).
//           Wp[64 k][65] with o_sw = (o&7)*8 + (o>>3)  (B LDS.32 conflict-free).
//           Thread: 4 b-pairs x 8 o, acc2[4][8] f32x2 = (C[b][o], C[b+1][o]).
//           Epilogue: 16 STG.128 into pixel-shuffle layout.

__device__ float g_xT32[256 * 64 * 256];  // [p][t][b], 16 MB

__device__ __forceinline__ uint32_t smem_u32(const void* p) {
    uint32_t a;
    asm("{ .reg .u64 t; cvta.to.shared.u64 t, %1; cvt.u32.u64 %0, t; }" : "=r"(a) : "l"(p));
    return a;
}
__device__ __forceinline__ void cp16(uint32_t sdst, const void* g) {
    asm volatile("cp.async.cg.shared.global [%0], [%1], 16;" :: "r"(sdst), "l"(g));
}
__device__ __forceinline__ unsigned long long dupf2(float v) {
    unsigned long long r;
    asm("mov.b64 %0, {%1, %1};" : "=l"(r) : "f"(v));
    return r;
}
__device__ __forceinline__ float2 unpackf2(unsigned long long v) {
    float2 r;
    asm("mov.b64 {%0, %1}, %2;" : "=f"(r.x), "=f"(r.y) : "l"(v));
    return r;
}

// ---------------------------------------------------------------------------
// Transpose: x[b][t][p] -> g_xT32[p*16384 + t*256 + b]
// grid (8 p-tiles, 8 b-tiles, 64 t), block (32, 8)
// ---------------------------------------------------------------------------
__global__ void transpose32_kernel(const float* __restrict__ x) {
    __shared__ float tile[32][33];
    int p0 = blockIdx.x * 32, b0 = blockIdx.y * 32, t = blockIdx.z;
    int tx = threadIdx.x, ty = threadIdx.y;
#pragma unroll
    for (int k = 0; k < 4; k++) {
        int br = ty + k * 8;
        tile[br][tx] = x[(size_t)(b0 + br) * 16384 + (size_t)t * 256 + p0 + tx];
    }
    __syncthreads();
#pragma unroll
    for (int k = 0; k < 4; k++) {
        int pr = ty + k * 8;
        g_xT32[(size_t)(p0 + pr) * 16384 + (size_t)t * 256 + b0 + tx] = tile[tx][pr];
    }
}

// ---------------------------------------------------------------------------
// GEMM: C[256 b x 64 o] per CTA. 256 threads = 32 tb (8 b each) x 8 to (8 o each).
// ---------------------------------------------------------------------------
#define WPROW 65
#define AS_F (64 * 256)              // 64 KB
#define WP_F (64 * WPROW)
#define SMEM_BYTES ((AS_F + WP_F + 64) * 4)

__global__ __launch_bounds__(256, 2) void gemm_kernel(const float* __restrict__ Wg_all,
                                                      const float* __restrict__ bias,
                                                      float* __restrict__ out) {
    extern __shared__ float smem[];
    float* As = smem;                   // [64 k][256 b]
    float* Wp = smem + AS_F;            // [64 k][WPROW], o-swizzled
    float* bias_s = smem + AS_F + WP_F; // [64]

    const int bn = blockIdx.x;   // 0..15 (o tile of 64)
    const int p  = blockIdx.y;
    const int tid = threadIdx.x;
    const int tb = tid >> 3;     // 0..31: b rows tb*8 .. tb*8+7
    const int to = tid & 7;      // 0..7:  o = bn*64 + to*8 + j

    // A: linear 64 KB copy of g_xT32 p-slice
    const float* Ag = g_xT32 + ((size_t)p << 14);
    uint32_t sA = smem_u32(As);
#pragma unroll
    for (int i = 0; i < 16; i++) {
        int idx = tid + i * 256;         // 4096 chunks of 16B
        cp16(sA + idx * 16, Ag + idx * 4);
    }
    if (tid < 16) cp16(smem_u32(bias_s) + tid * 16, bias + (size_t)p * 1024 + bn * 64 + tid * 4);
    asm volatile("cp.async.commit_group;");

    // W: [64 o][64 k] -> Wp[k][o_sw], o_sw = (o&7)*8 + (o>>3)
    const float* Wg = Wg_all + ((size_t)p << 16) + (size_t)(bn * 64) * 64;
#pragma unroll
    for (int i = 0; i < 4; i++) {
        int idx = tid + i * 256;          // 1024 float4s
        int o = idx >> 4;                 // 0..63
        int kc = (idx & 15) << 2;         // 0..60
        float4 v = *(const float4*)(Wg + o * 64 + kc);
        int o_sw = ((o & 7) << 3) + (o >> 3);
        Wp[(kc + 0) * WPROW + o_sw] = v.x;
        Wp[(kc + 1) * WPROW + o_sw] = v.y;
        Wp[(kc + 2) * WPROW + o_sw] = v.z;
        Wp[(kc + 3) * WPROW + o_sw] = v.w;
    }
    asm volatile("cp.async.wait_group 0;");
    __syncthreads();

    unsigned long long acc2[4][8];
#pragma unroll
    for (int i = 0; i < 4; i++)
#pragma unroll
        for (int j = 0; j < 8; j++) acc2[i][j] = 0ull;

    const float* Abase = As + tb * 8;
    const float* Bbase = Wp + to;

#pragma unroll 8
    for (int k = 0; k < 64; k++) {
        ulonglong2 A0 = *(const ulonglong2*)(Abase + k * 256);
        ulonglong2 A1 = *(const ulonglong2*)(Abase + k * 256 + 4);
        unsigned long long a2[4] = {A0.x, A0.y, A1.x, A1.y};
        const float* Bk = Bbase + k * WPROW;
        unsigned long long bd[8];
#pragma unroll
        for (int j = 0; j < 8; j++) bd[j] = dupf2(Bk[j * 8]);
#pragma unroll
        for (int i = 0; i < 4; i++)
#pragma unroll
            for (int j = 0; j < 8; j++) {
                asm("fma.rn.f32x2 %0, %1, %2, %0;"
                    : "+l"(acc2[i][j]) : "l"(a2[i]), "l"(bd[j]));
            }
    }

    // Epilogue: o0 = bn*64 + to*8; j 0..3 -> quad (t,ui), j 4..7 -> (t,ui+1)
    const int i4 = (p >> 4) << 2, j4 = (p & 15) << 2;
    int o0 = bn * 64 + to * 8;
    int t  = o0 >> 4;
    int ui = (o0 >> 2) & 3;               // 0 or 2
    int coloff0 = t * 4096 + (i4 + ui) * 64 + j4;
    int coloff1 = coloff0 + 64;           // ui+1
    float4 bv0 = *(const float4*)&bias_s[to * 8];
    float4 bv1 = *(const float4*)&bias_s[to * 8 + 4];
#pragma unroll
    for (int i = 0; i < 4; i++) {
        float2 c[8];
#pragma unroll
        for (int j = 0; j < 8; j++) c[j] = unpackf2(acc2[i][j]);
        size_t r0 = (size_t)(tb * 8 + 2 * i) * 262144;
        size_t r1 = r0 + 262144;
        *(float4*)(out + r0 + coloff0) =
            make_float4(c[0].x + bv0.x, c[1].x + bv0.y, c[2].x + bv0.z, c[3].x + bv0.w);
        *(float4*)(out + r0 + coloff1) =
            make_float4(c[4].x + bv1.x, c[5].x + bv1.y, c[6].x + bv1.z, c[7].x + bv1.w);
        *(float4*)(out + r1 + coloff0) =
            make_float4(c[0].y + bv0.x, c[1].y + bv0.y, c[2].y + bv0.z, c[3].y + bv0.w);
        *(float4*)(out + r1 + coloff1) =
            make_float4(c[4].y + bv1.x, c[5].y + bv1.y, c[6].y + bv1.z, c[7].y + bv1.w);
    }
}

extern "C" void kernel_launch(void* const* d_in, const int* in_sizes, int n_in,
                              void* d_out, int out_size) {
    const float* x = (const float*)d_in[0];   // (256, 64, 16, 16)
    const float* W = (const float*)d_in[1];   // (256, 1024, 64)
    const float* b = (const float*)d_in[2];   // (256, 1024)
    float* out = (float*)d_out;               // (256, 64, 64, 64)
    (void)in_sizes; (void)n_in; (void)out_size;

    cudaFuncSetAttribute(gemm_kernel, cudaFuncAttributeMaxDynamicSharedMemorySize, SMEM_BYTES);

    transpose32_kernel<<<dim3(8, 8, 64), dim3(32, 8)>>>(x);
    gemm_kernel<<<dim3(16, 256), 256, SMEM_BYTES>>>(W, b, out);
}

// round 12
// speedup vs baseline: 1.4220x; 1.0027x over previous
#include <cuda_runtime.h>
#include <cstdint>

// B=256, T=64 (K), S=16, U=4 -> P=256 pixels, O=1024 outputs/pixel.
//
// Model: fma floor 227k cyc (FFMA2 128 MAC/cyc/SM); crossbar charged per-lane
// bytes. Tile 8b x 8o (bytes/FFMA2 = 2.0) is optimal under the 128-reg /
// 2-CTA occupancy constraint. R12: same tile, B loads 8xLDS.32 -> 2xLDS.128
// (48B-stride group layout, bank-disjoint), dups via reg movs (alu pipe),
// unroll 16 for load-ahead ILP.
//
// kernel 1: transpose x -> g_xT32[p][t][b]
// kernel 2: CTA = (bn 16, p 256): C[256 b x 64 o] = A @ W^T + bias.

__device__ float g_xT32[256 * 64 * 256];  // [p][t][b], 16 MB

__device__ __forceinline__ uint32_t smem_u32(const void* p) {
    uint32_t a;
    asm("{ .reg .u64 t; cvta.to.shared.u64 t, %1; cvt.u32.u64 %0, t; }" : "=r"(a) : "l"(p));
    return a;
}
__device__ __forceinline__ void cp16(uint32_t sdst, const void* g) {
    asm volatile("cp.async.cg.shared.global [%0], [%1], 16;" :: "r"(sdst), "l"(g));
}
__device__ __forceinline__ unsigned long long dupf2(float v) {
    unsigned long long r;
    asm("mov.b64 %0, {%1, %1};" : "=l"(r) : "f"(v));
    return r;
}
__device__ __forceinline__ unsigned long long packf2(float x, float y) {
    unsigned long long r;
    asm("mov.b64 %0, {%1, %2};" : "=l"(r) : "f"(x), "f"(y));
    return r;
}
__device__ __forceinline__ float2 unpackf2(unsigned long long v) {
    float2 r;
    asm("mov.b64 {%0, %1}, %2;" : "=f"(r.x), "=f"(r.y) : "l"(v));
    return r;
}

// ---------------------------------------------------------------------------
// Transpose: x[b][t][p] -> g_xT32[p*16384 + t*256 + b]
// ---------------------------------------------------------------------------
__global__ void transpose32_kernel(const float* __restrict__ x) {
    __shared__ float tile[32][33];
    int p0 = blockIdx.x * 32, b0 = blockIdx.y * 32, t = blockIdx.z;
    int tx = threadIdx.x, ty = threadIdx.y;
#pragma unroll
    for (int k = 0; k < 4; k++) {
        int br = ty + k * 8;
        tile[br][tx] = x[(size_t)(b0 + br) * 16384 + (size_t)t * 256 + p0 + tx];
    }
    __syncthreads();
#pragma unroll
    for (int k = 0; k < 4; k++) {
        int pr = ty + k * 8;
        g_xT32[(size_t)(p0 + pr) * 16384 + (size_t)t * 256 + b0 + tx] = tile[tx][pr];
    }
}

// ---------------------------------------------------------------------------
// GEMM: C[256 b x 64 o] per CTA. 256 threads = 32 tb (8 b) x 8 to (8 o).
// Wp layout: value (k, o) at float k*WROW + (o>>3)*12 + (o&7)  [48B groups]
// ---------------------------------------------------------------------------
#define WROW 100
#define AS_F (64 * 256)              // 64 KB
#define WP_F (64 * WROW)             // 25.6 KB
#define SMEM_BYTES ((AS_F + WP_F + 64) * 4)

__global__ __launch_bounds__(256, 2) void gemm_kernel(const float* __restrict__ Wg_all,
                                                      const float* __restrict__ bias,
                                                      float* __restrict__ out) {
    extern __shared__ float smem[];
    float* As = smem;                   // [64 k][256 b]
    float* Wp = smem + AS_F;            // [64 k][WROW]
    float* bias_s = smem + AS_F + WP_F; // [64]

    const int bn = blockIdx.x;   // 0..15 (o tile of 64)
    const int p  = blockIdx.y;
    const int tid = threadIdx.x;
    const int tb = tid >> 3;     // 0..31: b rows tb*8 .. tb*8+7
    const int to = tid & 7;      // 0..7:  o = bn*64 + to*8 + j

    // A: linear 64 KB copy of g_xT32 p-slice
    const float* Ag = g_xT32 + ((size_t)p << 14);
    uint32_t sA = smem_u32(As);
#pragma unroll
    for (int i = 0; i < 16; i++) {
        int idx = tid + i * 256;         // 4096 chunks of 16B
        cp16(sA + idx * 16, Ag + idx * 4);
    }
    if (tid < 16) cp16(smem_u32(bias_s) + tid * 16, bias + (size_t)p * 1024 + bn * 64 + tid * 4);
    asm volatile("cp.async.commit_group;");

    // W: [64 o][64 k] -> Wp[k][(o>>3)*12 + (o&7)]
    const float* Wg = Wg_all + ((size_t)p << 16) + (size_t)(bn * 64) * 64;
#pragma unroll
    for (int i = 0; i < 4; i++) {
        int idx = tid + i * 256;          // 1024 float4s
        int o = idx >> 4;                 // 0..63
        int kc = (idx & 15) << 2;         // 0..60
        float4 v = *(const float4*)(Wg + o * 64 + kc);
        int od = ((o >> 3) * 12) + (o & 7);
        Wp[(kc + 0) * WROW + od] = v.x;
        Wp[(kc + 1) * WROW + od] = v.y;
        Wp[(kc + 2) * WROW + od] = v.z;
        Wp[(kc + 3) * WROW + od] = v.w;
    }
    asm volatile("cp.async.wait_group 0;");
    __syncthreads();

    unsigned long long acc2[4][8];
#pragma unroll
    for (int i = 0; i < 4; i++)
#pragma unroll
        for (int j = 0; j < 8; j++) acc2[i][j] = 0ull;

    const float* Abase = As + tb * 8;
    const float* Bbase = Wp + to * 12;

#pragma unroll 16
    for (int k = 0; k < 64; k++) {
        // A: 8 b as 4 natural b-pairs (2 x LDS.128)
        ulonglong2 A0 = *(const ulonglong2*)(Abase + k * 256);
        ulonglong2 A1 = *(const ulonglong2*)(Abase + k * 256 + 4);
        unsigned long long a2[4] = {A0.x, A0.y, A1.x, A1.y};
        // B: 8 o contiguous (2 x LDS.128), dup each scalar to both halves (alu movs)
        float4 B0 = *(const float4*)(Bbase + k * WROW);
        float4 B1 = *(const float4*)(Bbase + k * WROW + 4);
        unsigned long long bd[8];
        bd[0] = dupf2(B0.x); bd[1] = dupf2(B0.y);
        bd[2] = dupf2(B0.z); bd[3] = dupf2(B0.w);
        bd[4] = dupf2(B1.x); bd[5] = dupf2(B1.y);
        bd[6] = dupf2(B1.z); bd[7] = dupf2(B1.w);
#pragma unroll
        for (int i = 0; i < 4; i++)
#pragma unroll
            for (int j = 0; j < 8; j++) {
                asm("fma.rn.f32x2 %0, %1, %2, %0;"
                    : "+l"(acc2[i][j]) : "l"(a2[i]), "l"(bd[j]));
            }
    }

    // Epilogue: o0 = bn*64 + to*8; j 0..3 -> quad (t,ui), j 4..7 -> (t,ui+1)
    const int i4 = (p >> 4) << 2, j4 = (p & 15) << 2;
    int o0 = bn * 64 + to * 8;
    int t  = o0 >> 4;
    int ui = (o0 >> 2) & 3;               // 0 or 2
    int coloff0 = t * 4096 + (i4 + ui) * 64 + j4;
    int coloff1 = coloff0 + 64;           // ui+1
    float4 bv0 = *(const float4*)&bias_s[to * 8];
    float4 bv1 = *(const float4*)&bias_s[to * 8 + 4];
#pragma unroll
    for (int i = 0; i < 4; i++) {
        float2 c[8];
#pragma unroll
        for (int j = 0; j < 8; j++) c[j] = unpackf2(acc2[i][j]);
        size_t r0 = (size_t)(tb * 8 + 2 * i) * 262144;
        size_t r1 = r0 + 262144;
        *(float4*)(out + r0 + coloff0) =
            make_float4(c[0].x + bv0.x, c[1].x + bv0.y, c[2].x + bv0.z, c[3].x + bv0.w);
        *(float4*)(out + r0 + coloff1) =
            make_float4(c[4].x + bv1.x, c[5].x + bv1.y, c[6].x + bv1.z, c[7].x + bv1.w);
        *(float4*)(out + r1 + coloff0) =
            make_float4(c[0].y + bv0.x, c[1].y + bv0.y, c[2].y + bv0.z, c[3].y + bv0.w);
        *(float4*)(out + r1 + coloff1) =
            make_float4(c[4].y + bv1.x, c[5].y + bv1.y, c[6].y + bv1.z, c[7].y + bv1.w);
    }
}

extern "C" void kernel_launch(void* const* d_in, const int* in_sizes, int n_in,
                              void* d_out, int out_size) {
    const float* x = (const float*)d_in[0];   // (256, 64, 16, 16)
    const float* W = (const float*)d_in[1];   // (256, 1024, 64)
    const float* b = (const float*)d_in[2];   // (256, 1024)
    float* out = (float*)d_out;               // (256, 64, 64, 64)
    (void)in_sizes; (void)n_in; (void)out_size;

    cudaFuncSetAttribute(gemm_kernel, cudaFuncAttributeMaxDynamicSharedMemorySize, SMEM_BYTES);

    transpose32_kernel<<<dim3(8, 8, 64), dim3(32, 8)>>>(x);
    gemm_kernel<<<dim3(16, 256), 256, SMEM_BYTES>>>(W, b, out);
}